// round 1
// baseline (speedup 1.0000x reference)
#include <cuda_runtime.h>
#include <math.h>

#define Bsz 1024
#define Tsz 128
#define Fd 1024
#define Zd 256
#define Td 768
#define Hn 8
#define Dh 128

// Scratch (device globals; no allocation allowed)
__device__ float g_gamma[Bsz * Fd];
__device__ float g_beta[Bsz * Fd];
__device__ float g_h1[Bsz * Fd];
__device__ float g_out[Bsz * Fd];
__device__ float g_q[Bsz * Fd];
__device__ float g_qt[Bsz * Hn * Td];
__device__ float g_u[Bsz * Hn * Td];
__device__ float g_ctx[Bsz * Fd];
__device__ float g_ao[Bsz * Fd];

// ---------------------------------------------------------------------------
// Generic tiled SGEMM: C[m,n] = alpha * sum_k A[m,k] * B(n,k) + bias[n]
//   A: row-major, K contiguous: A[z*a_bs + m*lda + k]
//   B: BKM=true  (NT): B[z*b_bs + n*ldb + k]
//      BKM=false (NN): B[z*b_bs + k*ldb + n]
//   C: C[z*c_bs + m*ldc + n]
// BM=BN=64, BK=16, 256 threads, 4x4 per thread. All dims divide tile sizes.
// ---------------------------------------------------------------------------
template <bool BKM>
__global__ __launch_bounds__(256) void sgemm64(
    const float* __restrict__ A, int lda, int a_bs,
    const float* __restrict__ Bm, int ldb, int b_bs,
    const float* __restrict__ bias, int bias_bs,
    float* __restrict__ C, int ldc, int c_bs,
    int K, float alpha)
{
    __shared__ float As[16][64];
    __shared__ float Bs[16][64];
    const int tid = threadIdx.x;
    const int m0 = blockIdx.y * 64, n0 = blockIdx.x * 64, z = blockIdx.z;
    const float* Ap = A + (size_t)z * a_bs + (size_t)m0 * lda;
    const float* Bp = BKM ? (Bm + (size_t)z * b_bs + (size_t)n0 * ldb)
                          : (Bm + (size_t)z * b_bs + n0);
    float acc[4][4] = {};
    const int ty = tid >> 4, tx = tid & 15;

    for (int k0 = 0; k0 < K; k0 += 16) {
        {
            int m = tid >> 2, kq = tid & 3;
            const float4 v = *(const float4*)(Ap + (size_t)m * lda + k0 + kq * 4);
            As[kq * 4 + 0][m] = v.x; As[kq * 4 + 1][m] = v.y;
            As[kq * 4 + 2][m] = v.z; As[kq * 4 + 3][m] = v.w;
        }
        if (BKM) {
            int n = tid >> 2, kq = tid & 3;
            const float4 v = *(const float4*)(Bp + (size_t)n * ldb + k0 + kq * 4);
            Bs[kq * 4 + 0][n] = v.x; Bs[kq * 4 + 1][n] = v.y;
            Bs[kq * 4 + 2][n] = v.z; Bs[kq * 4 + 3][n] = v.w;
        } else {
            int kk = tid >> 4, nq = tid & 15;
            const float4 v = *(const float4*)(Bp + (size_t)(k0 + kk) * ldb + nq * 4);
            *(float4*)&Bs[kk][nq * 4] = v;
        }
        __syncthreads();
#pragma unroll
        for (int k = 0; k < 16; k++) {
            float a[4], b[4];
#pragma unroll
            for (int i = 0; i < 4; i++) a[i] = As[k][ty * 4 + i];
#pragma unroll
            for (int j = 0; j < 4; j++) b[j] = Bs[k][tx * 4 + j];
#pragma unroll
            for (int i = 0; i < 4; i++)
#pragma unroll
                for (int j = 0; j < 4; j++)
                    acc[i][j] = fmaf(a[i], b[j], acc[i][j]);
        }
        __syncthreads();
    }
#pragma unroll
    for (int i = 0; i < 4; i++) {
        int m = m0 + ty * 4 + i;
#pragma unroll
        for (int j = 0; j < 4; j++) {
            int n = n0 + tx * 4 + j;
            float v = acc[i][j] * alpha;
            if (bias) v += bias[(size_t)z * bias_bs + n];
            C[(size_t)z * c_bs + (size_t)m * ldc + n] = v;
        }
    }
}

// ---------------------------------------------------------------------------
// LayerNorm(h1) * g + b, then FiLM: * (1 + gamma) + beta. One block per row.
// ---------------------------------------------------------------------------
__global__ __launch_bounds__(256) void ln_film_kernel(
    const float* __restrict__ h1, const float* __restrict__ g,
    const float* __restrict__ bb, const float* __restrict__ gamma,
    const float* __restrict__ beta, float* __restrict__ out)
{
    int r = blockIdx.x, tid = threadIdx.x;
    __shared__ float red1[8], red2[8], mv[2];
    const float* row = h1 + (size_t)r * Fd;
    float v[4], s = 0.f, s2 = 0.f;
#pragma unroll
    for (int i = 0; i < 4; i++) {
        v[i] = row[tid + i * 256];
        s += v[i]; s2 += v[i] * v[i];
    }
#pragma unroll
    for (int o = 16; o; o >>= 1) {
        s += __shfl_xor_sync(~0u, s, o);
        s2 += __shfl_xor_sync(~0u, s2, o);
    }
    if ((tid & 31) == 0) { red1[tid >> 5] = s; red2[tid >> 5] = s2; }
    __syncthreads();
    if (tid == 0) {
        float a = 0.f, b2 = 0.f;
        for (int w = 0; w < 8; w++) { a += red1[w]; b2 += red2[w]; }
        mv[0] = a * (1.f / Fd); mv[1] = b2 * (1.f / Fd);
    }
    __syncthreads();
    float mu = mv[0], var = mv[1] - mu * mu;
    float rstd = rsqrtf(var + 1e-5f);
#pragma unroll
    for (int i = 0; i < 4; i++) {
        int f = tid + i * 256;
        float y = (v[i] - mu) * rstd * g[f] + bb[f];
        size_t idx = (size_t)r * Fd + f;
        out[idx] = y * (1.f + gamma[idx]) + beta[idx];
    }
}

// ---------------------------------------------------------------------------
// y = gelu(res + LayerNorm(ao)*g + b), exact gelu = x * Phi(x)
// ---------------------------------------------------------------------------
__global__ __launch_bounds__(256) void ln_add_gelu_kernel(
    const float* __restrict__ ao, const float* __restrict__ g,
    const float* __restrict__ bb, const float* __restrict__ res,
    float* __restrict__ y)
{
    int r = blockIdx.x, tid = threadIdx.x;
    __shared__ float red1[8], red2[8], mv[2];
    const float* row = ao + (size_t)r * Fd;
    float v[4], s = 0.f, s2 = 0.f;
#pragma unroll
    for (int i = 0; i < 4; i++) {
        v[i] = row[tid + i * 256];
        s += v[i]; s2 += v[i] * v[i];
    }
#pragma unroll
    for (int o = 16; o; o >>= 1) {
        s += __shfl_xor_sync(~0u, s, o);
        s2 += __shfl_xor_sync(~0u, s2, o);
    }
    if ((tid & 31) == 0) { red1[tid >> 5] = s; red2[tid >> 5] = s2; }
    __syncthreads();
    if (tid == 0) {
        float a = 0.f, b2 = 0.f;
        for (int w = 0; w < 8; w++) { a += red1[w]; b2 += red2[w]; }
        mv[0] = a * (1.f / Fd); mv[1] = b2 * (1.f / Fd);
    }
    __syncthreads();
    float mu = mv[0], var = mv[1] - mu * mu;
    float rstd = rsqrtf(var + 1e-5f);
#pragma unroll
    for (int i = 0; i < 4; i++) {
        int f = tid + i * 256;
        float t = res[(size_t)r * Fd + f] + ((v[i] - mu) * rstd * g[f] + bb[f]);
        y[(size_t)r * Fd + f] = t * normcdff(t);
    }
}

// ---------------------------------------------------------------------------
// Fused attention per batch row b (query length 1, reassociated):
//   scores[h,t] = sum_c qt[b,h,c] * text[b,t,c]   (qt pre-scaled by 1/sqrt(d))
//   online softmax over t-chunks of 16; accumulate u[h,c] = sum_t p * text
// warp = head h; lane owns c = lane + 32*i (24 regs each for q and u).
// Single pass over text_feat (read from HBM exactly once).
// smem: text chunk 16 x 768 at pitch 769 (conflict-free for both passes).
// ---------------------------------------------------------------------------
__global__ __launch_bounds__(256) void attn_kernel(
    const float* __restrict__ text, const int* __restrict__ att,
    const float* __restrict__ qt, float* __restrict__ u)
{
    extern __shared__ float sm[];  // 16 * 769 floats
    __shared__ int s_att[128];
    const int b = blockIdx.x, tid = threadIdx.x;
    const int h = tid >> 5, lane = tid & 31;

    float qreg[24], ureg[24];
    const float* qrow = qt + (size_t)b * (Hn * Td) + h * Td + lane;
#pragma unroll
    for (int i = 0; i < 24; i++) { qreg[i] = qrow[32 * i]; ureg[i] = 0.f; }
    for (int i = tid; i < 128; i += 256) s_att[i] = att[b * 128 + i];

    float m_run = -INFINITY, l_run = 0.f;
    const float* tb = text + (size_t)b * Tsz * Td;

    for (int tc = 0; tc < 8; tc++) {
        __syncthreads();  // previous chunk consumers done
        for (int i = tid; i < 16 * 768 / 4; i += 256) {
            float4 w = *(const float4*)(tb + tc * 16 * 768 + i * 4);
            int rr = (i * 4) / 768, cc = (i * 4) % 768;
            float* d = sm + rr * 769 + cc;
            d[0] = w.x; d[1] = w.y; d[2] = w.z; d[3] = w.w;
        }
        __syncthreads();

        float sc[16];
#pragma unroll
        for (int t = 0; t < 16; t++) {
            float a = 0.f;
            const float* tr = sm + t * 769 + lane;
#pragma unroll
            for (int i = 0; i < 24; i++) a = fmaf(qreg[i], tr[32 * i], a);
            sc[t] = a;
        }
#pragma unroll
        for (int t = 0; t < 16; t++)
#pragma unroll
            for (int o = 16; o; o >>= 1) sc[t] += __shfl_xor_sync(~0u, sc[t], o);

        float mx = m_run;
#pragma unroll
        for (int t = 0; t < 16; t++) {
            if (s_att[tc * 16 + t] == 0) sc[t] = -INFINITY;
            mx = fmaxf(mx, sc[t]);
        }
        float p[16], rs;
        if (mx == -INFINITY) {
            rs = 1.f;
#pragma unroll
            for (int t = 0; t < 16; t++) p[t] = 0.f;
        } else {
            rs = expf(m_run - mx);
#pragma unroll
            for (int t = 0; t < 16; t++)
                p[t] = (sc[t] == -INFINITY) ? 0.f : expf(sc[t] - mx);
        }
        float ps = 0.f;
#pragma unroll
        for (int t = 0; t < 16; t++) ps += p[t];
        l_run = l_run * rs + ps;
        m_run = mx;

#pragma unroll
        for (int i = 0; i < 24; i++) {
            float a = ureg[i] * rs;
            const float* tcol = sm + lane + 32 * i;
#pragma unroll
            for (int t = 0; t < 16; t++) a = fmaf(p[t], tcol[t * 769], a);
            ureg[i] = a;
        }
    }

    float inv = 1.f / l_run;
    float* urow = u + (size_t)b * (Hn * Td) + h * Td + lane;
#pragma unroll
    for (int i = 0; i < 24; i++) urow[32 * i] = ureg[i] * inv;
}

// ---------------------------------------------------------------------------
extern "C" void kernel_launch(void* const* d_in, const int* in_sizes, int n_in,
                              void* d_out, int out_size)
{
    const float* x    = (const float*)d_in[0];
    const float* z    = (const float*)d_in[1];
    const float* text = (const float*)d_in[2];
    const int*   att  = (const int*)d_in[3];
    const float* Wg = (const float*)d_in[4];  const float* bg = (const float*)d_in[5];
    const float* Wb = (const float*)d_in[6];  const float* bb = (const float*)d_in[7];
    const float* Wl = (const float*)d_in[8];  const float* bl = (const float*)d_in[9];
    const float* g1 = (const float*)d_in[10]; const float* b1 = (const float*)d_in[11];
    const float* Wq = (const float*)d_in[12]; const float* bq = (const float*)d_in[13];
    const float* Wk = (const float*)d_in[14]; /* bk (d_in[15]) is softmax-invariant: dropped */
    const float* Wv = (const float*)d_in[16]; const float* bv = (const float*)d_in[17];
    const float* Wo = (const float*)d_in[18]; const float* bo = (const float*)d_in[19];
    const float* g2 = (const float*)d_in[20]; const float* b2 = (const float*)d_in[21];
    float* y = (float*)d_out;

    float *p_gamma, *p_beta, *p_h1, *p_out, *p_q, *p_qt, *p_u, *p_ctx, *p_ao;
    cudaGetSymbolAddress((void**)&p_gamma, g_gamma);
    cudaGetSymbolAddress((void**)&p_beta,  g_beta);
    cudaGetSymbolAddress((void**)&p_h1,    g_h1);
    cudaGetSymbolAddress((void**)&p_out,   g_out);
    cudaGetSymbolAddress((void**)&p_q,     g_q);
    cudaGetSymbolAddress((void**)&p_qt,    g_qt);
    cudaGetSymbolAddress((void**)&p_u,     g_u);
    cudaGetSymbolAddress((void**)&p_ctx,   g_ctx);
    cudaGetSymbolAddress((void**)&p_ao,    g_ao);

    dim3 blk(256);

    // FiLM params: gamma = z @ Wg^T + bg, beta = z @ Wb^T + bb
    sgemm64<true><<<dim3(16, 16, 1), blk>>>(z, Zd, 0, Wg, Zd, 0, bg, 0,
                                            p_gamma, Fd, 0, Zd, 1.f);
    sgemm64<true><<<dim3(16, 16, 1), blk>>>(z, Zd, 0, Wb, Zd, 0, bb, 0,
                                            p_beta, Fd, 0, Zd, 1.f);
    // h1 = x @ Wl^T + bl
    sgemm64<true><<<dim3(16, 16, 1), blk>>>(x, Fd, 0, Wl, Fd, 0, bl, 0,
                                            p_h1, Fd, 0, Fd, 1.f);
    // out = LN(h1)*(1+gamma)+beta
    ln_film_kernel<<<1024, blk>>>(p_h1, g1, b1, p_gamma, p_beta, p_out);
    // q = out @ Wq^T + bq
    sgemm64<true><<<dim3(16, 16, 1), blk>>>(p_out, Fd, 0, Wq, Fd, 0, bq, 0,
                                            p_q, Fd, 0, Fd, 1.f);
    // qt[b,h,c] = (1/sqrt(d)) * sum_d q[b,h*128+d] * Wk[h*128+d, c]   (batched over h, NN)
    sgemm64<false><<<dim3(12, 16, 8), blk>>>(p_q, Fd, Dh, Wk, Td, Dh * Td,
                                             nullptr, 0, p_qt, Hn * Td, Td,
                                             Dh, 0.08838834764831845f);
    // fused attention: single pass over text_feat, outputs u[b,h,c]
    cudaFuncSetAttribute(attn_kernel, cudaFuncAttributeMaxDynamicSharedMemorySize,
                         16 * 769 * 4);
    attn_kernel<<<1024, 256, 16 * 769 * 4>>>(text, att, p_qt, p_u);
    // ctx[b,h*128+n] = sum_c u[b,h,c]*Wv[h*128+n,c] + bv[h*128+n]   (batched over h, NT)
    sgemm64<true><<<dim3(2, 16, 8), blk>>>(p_u, Hn * Td, Td, Wv, Td, Dh * Td,
                                           bv, Dh, p_ctx, Fd, Dh, Td, 1.f);
    // attn_out = ctx @ Wo^T + bo
    sgemm64<true><<<dim3(16, 16, 1), blk>>>(p_ctx, Fd, 0, Wo, Fd, 0, bo, 0,
                                            p_ao, Fd, 0, Fd, 1.f);
    // y = gelu(out + LN(attn_out))
    ln_add_gelu_kernel<<<1024, blk>>>(p_ao, g2, b2, p_out, y);
}

// round 2
// speedup vs baseline: 1.0241x; 1.0241x over previous
#include <cuda_runtime.h>
#include <math.h>

#define Bsz 1024
#define Tsz 128
#define Fd 1024
#define Zd 256
#define Td 768
#define Hn 8
#define Dh 128

// Scratch (device globals; no allocation allowed)
__device__ float g_gamma[Bsz * Fd];
__device__ float g_beta[Bsz * Fd];
__device__ float g_h1[Bsz * Fd];
__device__ float g_out[Bsz * Fd];
__device__ float g_q[Bsz * Fd];
__device__ float g_qt[Bsz * Hn * Td];
__device__ float g_u[Bsz * Hn * Td];
__device__ float g_ctx[Bsz * Fd];
__device__ float g_ao[Bsz * Fd];

// ---------------------------------------------------------------------------
// Register-blocked SGEMM: C[m,n] = alpha * sum_k A[m,k]*B(n,k) + bias[n]
//   Tile: BM=128, BN=64, BK=16. 256 threads, 8x4 micro-tile (32 acc regs).
//   Double-buffered smem, float4 global loads, conflict-free smem access.
//   A: row-major K-contig A[z*a_bs + m*lda + k]
//   B: BKM=true  (NT): B[z*b_bs + n*ldb + k]
//      BKM=false (NN): B[z*b_bs + k*ldb + n]
//   C: C[z*c_bs + m*ldc + n]
// All dims must divide tile sizes (true for every launch below).
// ---------------------------------------------------------------------------
template <bool BKM>
__global__ __launch_bounds__(256) void sgemm128(
    const float* __restrict__ A, int lda, int a_bs,
    const float* __restrict__ Bm, int ldb, int b_bs,
    const float* __restrict__ bias, int bias_bs,
    float* __restrict__ C, int ldc, int c_bs,
    int K, float alpha)
{
    __shared__ float As[2][16][128];
    __shared__ float Bs[2][16][64];
    const int tid = threadIdx.x;
    const int m0 = blockIdx.y * 128, n0 = blockIdx.x * 64, z = blockIdx.z;
    const float* Ap = A + (size_t)z * a_bs + (size_t)m0 * lda;
    const float* Bp = BKM ? (Bm + (size_t)z * b_bs + (size_t)n0 * ldb)
                          : (Bm + (size_t)z * b_bs + n0);
    const int ty = tid >> 4, tx = tid & 15;           // micro-tile coords
    const int am = tid & 127, akseg = tid >> 7;       // A load: 128 rows x 2 k-segs
    const int bn = tid & 63,  bkseg = tid >> 6;       // B NT load
    const int bk = tid >> 4,  bn4 = (tid & 15) * 4;   // B NN load

    float4 ra0, ra1, rb;

    auto ldg = [&](int k0) {
        const float* ar = Ap + (size_t)am * lda + k0 + akseg * 8;
        ra0 = *(const float4*)(ar);
        ra1 = *(const float4*)(ar + 4);
        if (BKM) rb = *(const float4*)(Bp + (size_t)bn * ldb + k0 + bkseg * 4);
        else     rb = *(const float4*)(Bp + (size_t)(k0 + bk) * ldb + bn4);
    };
    auto sts = [&](int buf) {
        As[buf][akseg * 8 + 0][am] = ra0.x;
        As[buf][akseg * 8 + 1][am] = ra0.y;
        As[buf][akseg * 8 + 2][am] = ra0.z;
        As[buf][akseg * 8 + 3][am] = ra0.w;
        As[buf][akseg * 8 + 4][am] = ra1.x;
        As[buf][akseg * 8 + 5][am] = ra1.y;
        As[buf][akseg * 8 + 6][am] = ra1.z;
        As[buf][akseg * 8 + 7][am] = ra1.w;
        if (BKM) {
            Bs[buf][bkseg * 4 + 0][bn] = rb.x;
            Bs[buf][bkseg * 4 + 1][bn] = rb.y;
            Bs[buf][bkseg * 4 + 2][bn] = rb.z;
            Bs[buf][bkseg * 4 + 3][bn] = rb.w;
        } else {
            *(float4*)&Bs[buf][bk][bn4] = rb;
        }
    };

    float acc[8][4] = {};
    ldg(0);
    sts(0);
    __syncthreads();

    const int nch = K >> 4;
    int cur = 0;
    for (int c = 0; c < nch; ++c) {
        if (c + 1 < nch) ldg((c + 1) << 4);
#pragma unroll
        for (int k = 0; k < 16; ++k) {
            float4 a0 = *(const float4*)&As[cur][k][ty * 8];
            float4 a1 = *(const float4*)&As[cur][k][ty * 8 + 4];
            float4 b4 = *(const float4*)&Bs[cur][k][tx * 4];
            float a[8] = {a0.x, a0.y, a0.z, a0.w, a1.x, a1.y, a1.z, a1.w};
            float b[4] = {b4.x, b4.y, b4.z, b4.w};
#pragma unroll
            for (int i = 0; i < 8; i++)
#pragma unroll
                for (int j = 0; j < 4; j++)
                    acc[i][j] = fmaf(a[i], b[j], acc[i][j]);
        }
        if (c + 1 < nch) sts(cur ^ 1);
        __syncthreads();
        cur ^= 1;
    }

    float bv[4] = {0.f, 0.f, 0.f, 0.f};
    if (bias) {
#pragma unroll
        for (int j = 0; j < 4; j++)
            bv[j] = bias[(size_t)z * bias_bs + n0 + tx * 4 + j];
    }
#pragma unroll
    for (int i = 0; i < 8; i++) {
        int m = m0 + ty * 8 + i;
        float4 o;
        o.x = fmaf(acc[i][0], alpha, bv[0]);
        o.y = fmaf(acc[i][1], alpha, bv[1]);
        o.z = fmaf(acc[i][2], alpha, bv[2]);
        o.w = fmaf(acc[i][3], alpha, bv[3]);
        *(float4*)&C[(size_t)z * c_bs + (size_t)m * ldc + n0 + tx * 4] = o;
    }
}

// ---------------------------------------------------------------------------
// LayerNorm(h1) * g + b, then FiLM: * (1 + gamma) + beta. One block per row.
// ---------------------------------------------------------------------------
__global__ __launch_bounds__(256) void ln_film_kernel(
    const float* __restrict__ h1, const float* __restrict__ g,
    const float* __restrict__ bb, const float* __restrict__ gamma,
    const float* __restrict__ beta, float* __restrict__ out)
{
    int r = blockIdx.x, tid = threadIdx.x;
    __shared__ float red1[8], red2[8], mv[2];
    const float* row = h1 + (size_t)r * Fd;
    float v[4], s = 0.f, s2 = 0.f;
#pragma unroll
    for (int i = 0; i < 4; i++) {
        v[i] = row[tid + i * 256];
        s += v[i]; s2 += v[i] * v[i];
    }
#pragma unroll
    for (int o = 16; o; o >>= 1) {
        s += __shfl_xor_sync(~0u, s, o);
        s2 += __shfl_xor_sync(~0u, s2, o);
    }
    if ((tid & 31) == 0) { red1[tid >> 5] = s; red2[tid >> 5] = s2; }
    __syncthreads();
    if (tid == 0) {
        float a = 0.f, b2 = 0.f;
        for (int w = 0; w < 8; w++) { a += red1[w]; b2 += red2[w]; }
        mv[0] = a * (1.f / Fd); mv[1] = b2 * (1.f / Fd);
    }
    __syncthreads();
    float mu = mv[0], var = mv[1] - mu * mu;
    float rstd = rsqrtf(var + 1e-5f);
#pragma unroll
    for (int i = 0; i < 4; i++) {
        int f = tid + i * 256;
        float y = (v[i] - mu) * rstd * g[f] + bb[f];
        size_t idx = (size_t)r * Fd + f;
        out[idx] = y * (1.f + gamma[idx]) + beta[idx];
    }
}

// ---------------------------------------------------------------------------
// y = gelu(res + LayerNorm(ao)*g + b), exact gelu = x * Phi(x)
// ---------------------------------------------------------------------------
__global__ __launch_bounds__(256) void ln_add_gelu_kernel(
    const float* __restrict__ ao, const float* __restrict__ g,
    const float* __restrict__ bb, const float* __restrict__ res,
    float* __restrict__ y)
{
    int r = blockIdx.x, tid = threadIdx.x;
    __shared__ float red1[8], red2[8], mv[2];
    const float* row = ao + (size_t)r * Fd;
    float v[4], s = 0.f, s2 = 0.f;
#pragma unroll
    for (int i = 0; i < 4; i++) {
        v[i] = row[tid + i * 256];
        s += v[i]; s2 += v[i] * v[i];
    }
#pragma unroll
    for (int o = 16; o; o >>= 1) {
        s += __shfl_xor_sync(~0u, s, o);
        s2 += __shfl_xor_sync(~0u, s2, o);
    }
    if ((tid & 31) == 0) { red1[tid >> 5] = s; red2[tid >> 5] = s2; }
    __syncthreads();
    if (tid == 0) {
        float a = 0.f, b2 = 0.f;
        for (int w = 0; w < 8; w++) { a += red1[w]; b2 += red2[w]; }
        mv[0] = a * (1.f / Fd); mv[1] = b2 * (1.f / Fd);
    }
    __syncthreads();
    float mu = mv[0], var = mv[1] - mu * mu;
    float rstd = rsqrtf(var + 1e-5f);
#pragma unroll
    for (int i = 0; i < 4; i++) {
        int f = tid + i * 256;
        float t = res[(size_t)r * Fd + f] + ((v[i] - mu) * rstd * g[f] + bb[f]);
        y[(size_t)r * Fd + f] = t * normcdff(t);
    }
}

// ---------------------------------------------------------------------------
// Fused attention per batch row b (query length 1, reassociated):
//   scores[h,t] = sum_c qt[b,h,c] * text[b,t,c]   (qt pre-scaled by 1/sqrt(d))
//   online softmax over t-chunks of 16; accumulate u[h,c] = sum_t p * text
// warp = head h; lane owns c = lane + 32*i. Text read from HBM exactly once.
// ---------------------------------------------------------------------------
__global__ __launch_bounds__(256) void attn_kernel(
    const float* __restrict__ text, const int* __restrict__ att,
    const float* __restrict__ qt, float* __restrict__ u)
{
    extern __shared__ float sm[];  // 16 * 769 floats
    __shared__ int s_att[128];
    const int b = blockIdx.x, tid = threadIdx.x;
    const int h = tid >> 5, lane = tid & 31;

    float qreg[24], ureg[24];
    const float* qrow = qt + (size_t)b * (Hn * Td) + h * Td + lane;
#pragma unroll
    for (int i = 0; i < 24; i++) { qreg[i] = qrow[32 * i]; ureg[i] = 0.f; }
    for (int i = tid; i < 128; i += 256) s_att[i] = att[b * 128 + i];

    float m_run = -INFINITY, l_run = 0.f;
    const float* tb = text + (size_t)b * Tsz * Td;

    for (int tc = 0; tc < 8; tc++) {
        __syncthreads();
        for (int i = tid; i < 16 * 768 / 4; i += 256) {
            float4 w = *(const float4*)(tb + tc * 16 * 768 + i * 4);
            int rr = (i * 4) / 768, cc = (i * 4) % 768;
            float* d = sm + rr * 769 + cc;
            d[0] = w.x; d[1] = w.y; d[2] = w.z; d[3] = w.w;
        }
        __syncthreads();

        float sc[16];
#pragma unroll
        for (int t = 0; t < 16; t++) {
            float a = 0.f;
            const float* tr = sm + t * 769 + lane;
#pragma unroll
            for (int i = 0; i < 24; i++) a = fmaf(qreg[i], tr[32 * i], a);
            sc[t] = a;
        }
#pragma unroll
        for (int t = 0; t < 16; t++)
#pragma unroll
            for (int o = 16; o; o >>= 1) sc[t] += __shfl_xor_sync(~0u, sc[t], o);

        float mx = m_run;
#pragma unroll
        for (int t = 0; t < 16; t++) {
            if (s_att[tc * 16 + t] == 0) sc[t] = -INFINITY;
            mx = fmaxf(mx, sc[t]);
        }
        float p[16], rs;
        if (mx == -INFINITY) {
            rs = 1.f;
#pragma unroll
            for (int t = 0; t < 16; t++) p[t] = 0.f;
        } else {
            rs = expf(m_run - mx);
#pragma unroll
            for (int t = 0; t < 16; t++)
                p[t] = (sc[t] == -INFINITY) ? 0.f : expf(sc[t] - mx);
        }
        float ps = 0.f;
#pragma unroll
        for (int t = 0; t < 16; t++) ps += p[t];
        l_run = l_run * rs + ps;
        m_run = mx;

#pragma unroll
        for (int i = 0; i < 24; i++) {
            float a = ureg[i] * rs;
            const float* tcol = sm + lane + 32 * i;
#pragma unroll
            for (int t = 0; t < 16; t++) a = fmaf(p[t], tcol[t * 769], a);
            ureg[i] = a;
        }
    }

    float inv = 1.f / l_run;
    float* urow = u + (size_t)b * (Hn * Td) + h * Td + lane;
#pragma unroll
    for (int i = 0; i < 24; i++) urow[32 * i] = ureg[i] * inv;
}

// ---------------------------------------------------------------------------
extern "C" void kernel_launch(void* const* d_in, const int* in_sizes, int n_in,
                              void* d_out, int out_size)
{
    const float* x    = (const float*)d_in[0];
    const float* z    = (const float*)d_in[1];
    const float* text = (const float*)d_in[2];
    const int*   att  = (const int*)d_in[3];
    const float* Wg = (const float*)d_in[4];  const float* bg = (const float*)d_in[5];
    const float* Wb = (const float*)d_in[6];  const float* bb = (const float*)d_in[7];
    const float* Wl = (const float*)d_in[8];  const float* bl = (const float*)d_in[9];
    const float* g1 = (const float*)d_in[10]; const float* b1 = (const float*)d_in[11];
    const float* Wq = (const float*)d_in[12]; const float* bq = (const float*)d_in[13];
    const float* Wk = (const float*)d_in[14]; /* bk (d_in[15]) softmax-invariant: dropped */
    const float* Wv = (const float*)d_in[16]; const float* bv = (const float*)d_in[17];
    const float* Wo = (const float*)d_in[18]; const float* bo = (const float*)d_in[19];
    const float* g2 = (const float*)d_in[20]; const float* b2 = (const float*)d_in[21];
    float* y = (float*)d_out;

    float *p_gamma, *p_beta, *p_h1, *p_out, *p_q, *p_qt, *p_u, *p_ctx, *p_ao;
    cudaGetSymbolAddress((void**)&p_gamma, g_gamma);
    cudaGetSymbolAddress((void**)&p_beta,  g_beta);
    cudaGetSymbolAddress((void**)&p_h1,    g_h1);
    cudaGetSymbolAddress((void**)&p_out,   g_out);
    cudaGetSymbolAddress((void**)&p_q,     g_q);
    cudaGetSymbolAddress((void**)&p_qt,    g_qt);
    cudaGetSymbolAddress((void**)&p_u,     g_u);
    cudaGetSymbolAddress((void**)&p_ctx,   g_ctx);
    cudaGetSymbolAddress((void**)&p_ao,    g_ao);

    dim3 blk(256);

    // gamma = z @ Wg^T + bg ; beta = z @ Wb^T + bb   [1024x1024, K=256]
    sgemm128<true><<<dim3(16, 8, 1), blk>>>(z, Zd, 0, Wg, Zd, 0, bg, 0,
                                            p_gamma, Fd, 0, Zd, 1.f);
    sgemm128<true><<<dim3(16, 8, 1), blk>>>(z, Zd, 0, Wb, Zd, 0, bb, 0,
                                            p_beta, Fd, 0, Zd, 1.f);
    // h1 = x @ Wl^T + bl   [1024x1024, K=1024]
    sgemm128<true><<<dim3(16, 8, 1), blk>>>(x, Fd, 0, Wl, Fd, 0, bl, 0,
                                            p_h1, Fd, 0, Fd, 1.f);
    // out = LN(h1)*(1+gamma)+beta
    ln_film_kernel<<<1024, blk>>>(p_h1, g1, b1, p_gamma, p_beta, p_out);
    // q = out @ Wq^T + bq
    sgemm128<true><<<dim3(16, 8, 1), blk>>>(p_out, Fd, 0, Wq, Fd, 0, bq, 0,
                                            p_q, Fd, 0, Fd, 1.f);
    // qt[b,h,c] = (1/sqrt(d)) * sum_d q[b,h*128+d] * Wk[h*128+d, c]  (NN, batched h)
    sgemm128<false><<<dim3(12, 8, 8), blk>>>(p_q, Fd, Dh, Wk, Td, Dh * Td,
                                             nullptr, 0, p_qt, Hn * Td, Td,
                                             Dh, 0.08838834764831845f);
    // fused attention: single pass over text_feat, outputs normalized u[b,h,c]
    cudaFuncSetAttribute(attn_kernel, cudaFuncAttributeMaxDynamicSharedMemorySize,
                         16 * 769 * 4);
    attn_kernel<<<1024, 256, 16 * 769 * 4>>>(text, att, p_qt, p_u);
    // ctx[b,h*128+n] = sum_c u[b,h,c]*Wv[h*128+n,c] + bv  (NT, batched h)
    sgemm128<true><<<dim3(2, 8, 8), blk>>>(p_u, Hn * Td, Td, Wv, Td, Dh * Td,
                                           bv, Dh, p_ctx, Fd, Dh, Td, 1.f);
    // attn_out = ctx @ Wo^T + bo
    sgemm128<true><<<dim3(16, 8, 1), blk>>>(p_ctx, Fd, 0, Wo, Fd, 0, bo, 0,
                                            p_ao, Fd, 0, Fd, 1.f);
    // y = gelu(out + LN(attn_out))
    ln_add_gelu_kernel<<<1024, blk>>>(p_ao, g2, b2, p_out, y);
}

// round 3
// speedup vs baseline: 1.1938x; 1.1658x over previous
#include <cuda_runtime.h>
#include <cuda_bf16.h>
#include <math.h>

#define Bsz 1024
#define Tsz 128
#define Fd 1024
#define Zd 256
#define Td 768
#define Hn 8
#define Dh 128

// fp32 scratch
__device__ float g_gamma[Bsz * Fd];
__device__ float g_beta[Bsz * Fd];
__device__ float g_h1[Bsz * Fd];
__device__ float g_out[Bsz * Fd];
__device__ float g_q[Bsz * Fd];
__device__ float g_qt[Bsz * Hn * Td];
__device__ float g_u[Bsz * Hn * Td];
__device__ float g_ctx[Bsz * Fd];
__device__ float g_ao[Bsz * Fd];

// bf16 hi/lo pre-split weights
__device__ __nv_bfloat16 g_Wg_h[Fd * Zd],  g_Wg_l[Fd * Zd];
__device__ __nv_bfloat16 g_Wb_h[Fd * Zd],  g_Wb_l[Fd * Zd];
__device__ __nv_bfloat16 g_Wl_h[Fd * Fd],  g_Wl_l[Fd * Fd];
__device__ __nv_bfloat16 g_Wq_h[Fd * Fd],  g_Wq_l[Fd * Fd];
__device__ __nv_bfloat16 g_Wo_h[Fd * Fd],  g_Wo_l[Fd * Fd];
__device__ __nv_bfloat16 g_Wv_h[Fd * Td],  g_Wv_l[Fd * Td];
__device__ __nv_bfloat16 g_WkT_h[Hn * Td * Dh], g_WkT_l[Hn * Td * Dh];

// ---------------------------------------------------------------------------
// Split fp32 -> bf16 hi + bf16 lo (residual). 4 elements per thread.
// ---------------------------------------------------------------------------
__global__ __launch_bounds__(256) void split_kernel(
    const float* __restrict__ w, __nv_bfloat16* __restrict__ h,
    __nv_bfloat16* __restrict__ l)
{
    int i = (blockIdx.x * 256 + threadIdx.x) * 4;
    float4 v = *(const float4*)(w + i);
    float vv[4] = {v.x, v.y, v.z, v.w};
#pragma unroll
    for (int j = 0; j < 4; j++) {
        __nv_bfloat16 hi = __float2bfloat16(vv[j]);
        h[i + j] = hi;
        l[i + j] = __float2bfloat16(vv[j] - __bfloat162float(hi));
    }
}

// Split + transpose Wk: out[(hh*768 + c)*128 + d] = Wk[(hh*128 + d)*768 + c]
__global__ __launch_bounds__(256) void splitT_wk(
    const float* __restrict__ w, __nv_bfloat16* __restrict__ h,
    __nv_bfloat16* __restrict__ l)
{
    int idx = blockIdx.x * 256 + threadIdx.x;   // 786432 total
    int d = idx & 127;
    int c = (idx >> 7) % Td;
    int hh = idx / (128 * Td);
    float v = w[((size_t)hh * 128 + d) * Td + c];
    __nv_bfloat16 hi = __float2bfloat16(v);
    h[idx] = hi;
    l[idx] = __float2bfloat16(v - __bfloat162float(hi));
}

// ---------------------------------------------------------------------------
// Tensor-core GEMM (NT): C[m,n] = alpha * sum_k A[m,k]*B[n,k] + bias[n]
//   A fp32 (split to bf16 hi/lo on the fly), B pre-split bf16 hi/lo.
//   3-pass Markidis: acc += Ah*Bh + Ah*Bl + Al*Bh  (err ~2^-18)
//   BM=128 BN=64 BK=32, 256 thr (8 warps 4Mx2N, warp tile 32x32),
//   mma.sync.m16n8k16.bf16. smem pitch 40 bf16 (conflict-free frags).
// ---------------------------------------------------------------------------
__device__ __forceinline__ void mma16816(float* c, const unsigned* a, const unsigned* b)
{
    asm volatile(
        "mma.sync.aligned.m16n8k16.row.col.f32.bf16.bf16.f32 "
        "{%0,%1,%2,%3}, {%4,%5,%6,%7}, {%8,%9}, {%0,%1,%2,%3};\n"
        : "+f"(c[0]), "+f"(c[1]), "+f"(c[2]), "+f"(c[3])
        : "r"(a[0]), "r"(a[1]), "r"(a[2]), "r"(a[3]), "r"(b[0]), "r"(b[1]));
}

#define PK 40  // smem pitch in bf16

__global__ __launch_bounds__(256) void bgemm(
    const float* __restrict__ A, int lda, int a_bs,
    const __nv_bfloat16* __restrict__ Bh_g, const __nv_bfloat16* __restrict__ Bl_g,
    int ldb, int b_bs,
    const float* __restrict__ bias, int bias_bs,
    float* __restrict__ C, int ldc, int c_bs,
    int K, float alpha)
{
    __shared__ __nv_bfloat16 sAh[128 * PK], sAl[128 * PK];
    __shared__ __nv_bfloat16 sBh[64 * PK],  sBl[64 * PK];

    const int tid = threadIdx.x;
    const int lane = tid & 31, warp = tid >> 5;
    const int wm = warp & 3, wn = warp >> 2;
    const int m0 = blockIdx.y * 128, n0 = blockIdx.x * 64, z = blockIdx.z;

    const float* Ap = A + (size_t)z * a_bs + (size_t)m0 * lda;
    const __nv_bfloat16* Bph = Bh_g + (size_t)z * b_bs + (size_t)n0 * ldb;
    const __nv_bfloat16* Bpl = Bl_g + (size_t)z * b_bs + (size_t)n0 * ldb;

    // global-load assignments
    const int ar = tid >> 1, ak = (tid & 1) * 16;       // A: 128 rows x 32k
    const int br = tid >> 2, bkofs = (tid & 3) * 8;     // B: 64 rows x 32k (8 bf16 each)

    float4 av[4];
    uint4 bvh, bvl;

    auto ldg = [&](int k0) {
        const float* ap = Ap + (size_t)ar * lda + k0 + ak;
        av[0] = *(const float4*)(ap);
        av[1] = *(const float4*)(ap + 4);
        av[2] = *(const float4*)(ap + 8);
        av[3] = *(const float4*)(ap + 12);
        bvh = *(const uint4*)(Bph + (size_t)br * ldb + k0 + bkofs);
        bvl = *(const uint4*)(Bpl + (size_t)br * ldb + k0 + bkofs);
    };
    auto sts = [&]() {
        const float* af = (const float*)av;
#pragma unroll
        for (int j = 0; j < 16; j++) {
            float v = af[j];
            __nv_bfloat16 hi = __float2bfloat16(v);
            sAh[ar * PK + ak + j] = hi;
            sAl[ar * PK + ak + j] = __float2bfloat16(v - __bfloat162float(hi));
        }
        *(uint4*)&sBh[br * PK + bkofs] = bvh;
        *(uint4*)&sBl[br * PK + bkofs] = bvl;
    };

    float acc[2][4][4] = {};
    const int gid = lane >> 2, tig = lane & 3;

    ldg(0);
    const int nit = K >> 5;
    for (int it = 0; it < nit; ++it) {
        __syncthreads();
        sts();
        __syncthreads();
        if (it + 1 < nit) ldg((it + 1) << 5);

#pragma unroll
        for (int kk = 0; kk < 32; kk += 16) {
            unsigned ah[2][4], al[2][4], bh[4][2], bl[4][2];
#pragma unroll
            for (int mr = 0; mr < 2; mr++) {
                int r = wm * 32 + mr * 16 + gid;
                int cb = kk + tig * 2;
                ah[mr][0] = *(const unsigned*)&sAh[r * PK + cb];
                ah[mr][1] = *(const unsigned*)&sAh[(r + 8) * PK + cb];
                ah[mr][2] = *(const unsigned*)&sAh[r * PK + cb + 8];
                ah[mr][3] = *(const unsigned*)&sAh[(r + 8) * PK + cb + 8];
                al[mr][0] = *(const unsigned*)&sAl[r * PK + cb];
                al[mr][1] = *(const unsigned*)&sAl[(r + 8) * PK + cb];
                al[mr][2] = *(const unsigned*)&sAl[r * PK + cb + 8];
                al[mr][3] = *(const unsigned*)&sAl[(r + 8) * PK + cb + 8];
            }
#pragma unroll
            for (int nc = 0; nc < 4; nc++) {
                int n = wn * 32 + nc * 8 + gid;
                int cb = kk + tig * 2;
                bh[nc][0] = *(const unsigned*)&sBh[n * PK + cb];
                bh[nc][1] = *(const unsigned*)&sBh[n * PK + cb + 8];
                bl[nc][0] = *(const unsigned*)&sBl[n * PK + cb];
                bl[nc][1] = *(const unsigned*)&sBl[n * PK + cb + 8];
            }
#pragma unroll
            for (int mr = 0; mr < 2; mr++)
#pragma unroll
                for (int nc = 0; nc < 4; nc++) {
                    mma16816(acc[mr][nc], ah[mr], bh[nc]);
                    mma16816(acc[mr][nc], ah[mr], bl[nc]);
                    mma16816(acc[mr][nc], al[mr], bh[nc]);
                }
        }
    }

    // epilogue
#pragma unroll
    for (int mr = 0; mr < 2; mr++) {
#pragma unroll
        for (int nc = 0; nc < 4; nc++) {
            int m = m0 + wm * 32 + mr * 16 + gid;
            int n = n0 + wn * 32 + nc * 8 + tig * 2;
            float b0 = 0.f, b1 = 0.f;
            if (bias) {
                b0 = bias[(size_t)z * bias_bs + n];
                b1 = bias[(size_t)z * bias_bs + n + 1];
            }
            float2 o0, o1;
            o0.x = fmaf(acc[mr][nc][0], alpha, b0);
            o0.y = fmaf(acc[mr][nc][1], alpha, b1);
            o1.x = fmaf(acc[mr][nc][2], alpha, b0);
            o1.y = fmaf(acc[mr][nc][3], alpha, b1);
            *(float2*)&C[(size_t)z * c_bs + (size_t)m * ldc + n] = o0;
            *(float2*)&C[(size_t)z * c_bs + (size_t)(m + 8) * ldc + n] = o1;
        }
    }
}

// ---------------------------------------------------------------------------
// LayerNorm(h1) * g + b, then FiLM: * (1 + gamma) + beta. One block per row.
// ---------------------------------------------------------------------------
__global__ __launch_bounds__(256) void ln_film_kernel(
    const float* __restrict__ h1, const float* __restrict__ g,
    const float* __restrict__ bb, const float* __restrict__ gamma,
    const float* __restrict__ beta, float* __restrict__ out)
{
    int r = blockIdx.x, tid = threadIdx.x;
    __shared__ float red1[8], red2[8], mv[2];
    const float* row = h1 + (size_t)r * Fd;
    float v[4], s = 0.f, s2 = 0.f;
#pragma unroll
    for (int i = 0; i < 4; i++) {
        v[i] = row[tid + i * 256];
        s += v[i]; s2 += v[i] * v[i];
    }
#pragma unroll
    for (int o = 16; o; o >>= 1) {
        s += __shfl_xor_sync(~0u, s, o);
        s2 += __shfl_xor_sync(~0u, s2, o);
    }
    if ((tid & 31) == 0) { red1[tid >> 5] = s; red2[tid >> 5] = s2; }
    __syncthreads();
    if (tid == 0) {
        float a = 0.f, b2 = 0.f;
        for (int w = 0; w < 8; w++) { a += red1[w]; b2 += red2[w]; }
        mv[0] = a * (1.f / Fd); mv[1] = b2 * (1.f / Fd);
    }
    __syncthreads();
    float mu = mv[0], var = mv[1] - mu * mu;
    float rstd = rsqrtf(var + 1e-5f);
#pragma unroll
    for (int i = 0; i < 4; i++) {
        int f = tid + i * 256;
        float y = (v[i] - mu) * rstd * g[f] + bb[f];
        size_t idx = (size_t)r * Fd + f;
        out[idx] = y * (1.f + gamma[idx]) + beta[idx];
    }
}

// ---------------------------------------------------------------------------
// y = gelu(res + LayerNorm(ao)*g + b), exact gelu = x * Phi(x)
// ---------------------------------------------------------------------------
__global__ __launch_bounds__(256) void ln_add_gelu_kernel(
    const float* __restrict__ ao, const float* __restrict__ g,
    const float* __restrict__ bb, const float* __restrict__ res,
    float* __restrict__ y)
{
    int r = blockIdx.x, tid = threadIdx.x;
    __shared__ float red1[8], red2[8], mv[2];
    const float* row = ao + (size_t)r * Fd;
    float v[4], s = 0.f, s2 = 0.f;
#pragma unroll
    for (int i = 0; i < 4; i++) {
        v[i] = row[tid + i * 256];
        s += v[i]; s2 += v[i] * v[i];
    }
#pragma unroll
    for (int o = 16; o; o >>= 1) {
        s += __shfl_xor_sync(~0u, s, o);
        s2 += __shfl_xor_sync(~0u, s2, o);
    }
    if ((tid & 31) == 0) { red1[tid >> 5] = s; red2[tid >> 5] = s2; }
    __syncthreads();
    if (tid == 0) {
        float a = 0.f, b2 = 0.f;
        for (int w = 0; w < 8; w++) { a += red1[w]; b2 += red2[w]; }
        mv[0] = a * (1.f / Fd); mv[1] = b2 * (1.f / Fd);
    }
    __syncthreads();
    float mu = mv[0], var = mv[1] - mu * mu;
    float rstd = rsqrtf(var + 1e-5f);
#pragma unroll
    for (int i = 0; i < 4; i++) {
        int f = tid + i * 256;
        float t = res[(size_t)r * Fd + f] + ((v[i] - mu) * rstd * g[f] + bb[f]);
        y[(size_t)r * Fd + f] = t * normcdff(t);
    }
}

// ---------------------------------------------------------------------------
// Fused attention per batch b (query length 1, reassociated):
//   scores[h,t] = sum_c qt[b,h,c]*text[b,t,c]; online softmax over t-chunks;
//   u[h,c] = (1/l) sum_t p * text. Text read from HBM exactly once.
// ---------------------------------------------------------------------------
__global__ __launch_bounds__(256) void attn_kernel(
    const float* __restrict__ text, const int* __restrict__ att,
    const float* __restrict__ qt, float* __restrict__ u)
{
    extern __shared__ float sm[];  // 16 * 769 floats
    __shared__ int s_att[128];
    const int b = blockIdx.x, tid = threadIdx.x;
    const int h = tid >> 5, lane = tid & 31;

    float qreg[24], ureg[24];
    const float* qrow = qt + (size_t)b * (Hn * Td) + h * Td + lane;
#pragma unroll
    for (int i = 0; i < 24; i++) { qreg[i] = qrow[32 * i]; ureg[i] = 0.f; }
    for (int i = tid; i < 128; i += 256) s_att[i] = att[b * 128 + i];

    float m_run = -INFINITY, l_run = 0.f;
    const float* tb = text + (size_t)b * Tsz * Td;

    for (int tc = 0; tc < 8; tc++) {
        __syncthreads();
        for (int i = tid; i < 16 * 768 / 4; i += 256) {
            float4 w = *(const float4*)(tb + tc * 16 * 768 + i * 4);
            int rr = (i * 4) / 768, cc = (i * 4) % 768;
            float* d = sm + rr * 769 + cc;
            d[0] = w.x; d[1] = w.y; d[2] = w.z; d[3] = w.w;
        }
        __syncthreads();

        float sc[16];
#pragma unroll
        for (int t = 0; t < 16; t++) {
            float a = 0.f;
            const float* tr = sm + t * 769 + lane;
#pragma unroll
            for (int i = 0; i < 24; i++) a = fmaf(qreg[i], tr[32 * i], a);
            sc[t] = a;
        }
#pragma unroll
        for (int t = 0; t < 16; t++)
#pragma unroll
            for (int o = 16; o; o >>= 1) sc[t] += __shfl_xor_sync(~0u, sc[t], o);

        float mx = m_run;
#pragma unroll
        for (int t = 0; t < 16; t++) {
            if (s_att[tc * 16 + t] == 0) sc[t] = -INFINITY;
            mx = fmaxf(mx, sc[t]);
        }
        float p[16], rs;
        if (mx == -INFINITY) {
            rs = 1.f;
#pragma unroll
            for (int t = 0; t < 16; t++) p[t] = 0.f;
        } else {
            rs = expf(m_run - mx);
#pragma unroll
            for (int t = 0; t < 16; t++)
                p[t] = (sc[t] == -INFINITY) ? 0.f : expf(sc[t] - mx);
        }
        float ps = 0.f;
#pragma unroll
        for (int t = 0; t < 16; t++) ps += p[t];
        l_run = l_run * rs + ps;
        m_run = mx;

#pragma unroll
        for (int i = 0; i < 24; i++) {
            float a = ureg[i] * rs;
            const float* tcol = sm + lane + 32 * i;
#pragma unroll
            for (int t = 0; t < 16; t++) a = fmaf(p[t], tcol[t * 769], a);
            ureg[i] = a;
        }
    }

    float inv = 1.f / l_run;
    float* urow = u + (size_t)b * (Hn * Td) + h * Td + lane;
#pragma unroll
    for (int i = 0; i < 24; i++) urow[32 * i] = ureg[i] * inv;
}

// ---------------------------------------------------------------------------
extern "C" void kernel_launch(void* const* d_in, const int* in_sizes, int n_in,
                              void* d_out, int out_size)
{
    const float* x    = (const float*)d_in[0];
    const float* z    = (const float*)d_in[1];
    const float* text = (const float*)d_in[2];
    const int*   att  = (const int*)d_in[3];
    const float* Wg = (const float*)d_in[4];  const float* bg = (const float*)d_in[5];
    const float* Wb = (const float*)d_in[6];  const float* bb = (const float*)d_in[7];
    const float* Wl = (const float*)d_in[8];  const float* bl = (const float*)d_in[9];
    const float* g1 = (const float*)d_in[10]; const float* b1 = (const float*)d_in[11];
    const float* Wq = (const float*)d_in[12]; const float* bq = (const float*)d_in[13];
    const float* Wk = (const float*)d_in[14]; /* bk (d_in[15]) softmax-invariant: dropped */
    const float* Wv = (const float*)d_in[16]; const float* bv = (const float*)d_in[17];
    const float* Wo = (const float*)d_in[18]; const float* bo = (const float*)d_in[19];
    const float* g2 = (const float*)d_in[20]; const float* b2 = (const float*)d_in[21];
    float* y = (float*)d_out;

    float *p_gamma, *p_beta, *p_h1, *p_out, *p_q, *p_qt, *p_u, *p_ctx, *p_ao;
    cudaGetSymbolAddress((void**)&p_gamma, g_gamma);
    cudaGetSymbolAddress((void**)&p_beta,  g_beta);
    cudaGetSymbolAddress((void**)&p_h1,    g_h1);
    cudaGetSymbolAddress((void**)&p_out,   g_out);
    cudaGetSymbolAddress((void**)&p_q,     g_q);
    cudaGetSymbolAddress((void**)&p_qt,    g_qt);
    cudaGetSymbolAddress((void**)&p_u,     g_u);
    cudaGetSymbolAddress((void**)&p_ctx,   g_ctx);
    cudaGetSymbolAddress((void**)&p_ao,    g_ao);

    __nv_bfloat16 *wg_h, *wg_l, *wb_h, *wb_l, *wl_h, *wl_l, *wq_h, *wq_l;
    __nv_bfloat16 *wo_h, *wo_l, *wv_h, *wv_l, *wk_h, *wk_l;
    cudaGetSymbolAddress((void**)&wg_h, g_Wg_h); cudaGetSymbolAddress((void**)&wg_l, g_Wg_l);
    cudaGetSymbolAddress((void**)&wb_h, g_Wb_h); cudaGetSymbolAddress((void**)&wb_l, g_Wb_l);
    cudaGetSymbolAddress((void**)&wl_h, g_Wl_h); cudaGetSymbolAddress((void**)&wl_l, g_Wl_l);
    cudaGetSymbolAddress((void**)&wq_h, g_Wq_h); cudaGetSymbolAddress((void**)&wq_l, g_Wq_l);
    cudaGetSymbolAddress((void**)&wo_h, g_Wo_h); cudaGetSymbolAddress((void**)&wo_l, g_Wo_l);
    cudaGetSymbolAddress((void**)&wv_h, g_Wv_h); cudaGetSymbolAddress((void**)&wv_l, g_Wv_l);
    cudaGetSymbolAddress((void**)&wk_h, g_WkT_h); cudaGetSymbolAddress((void**)&wk_l, g_WkT_l);

    dim3 blk(256);

    // weight pre-split (bf16 hi/lo); Wk also transposed per head
    split_kernel<<<(Fd * Zd) / 1024, blk>>>(Wg, wg_h, wg_l);
    split_kernel<<<(Fd * Zd) / 1024, blk>>>(Wb, wb_h, wb_l);
    split_kernel<<<(Fd * Fd) / 1024, blk>>>(Wl, wl_h, wl_l);
    split_kernel<<<(Fd * Fd) / 1024, blk>>>(Wq, wq_h, wq_l);
    split_kernel<<<(Fd * Fd) / 1024, blk>>>(Wo, wo_h, wo_l);
    split_kernel<<<(Fd * Td) / 1024, blk>>>(Wv, wv_h, wv_l);
    splitT_wk<<<(Hn * Td * Dh) / 256, blk>>>(Wk, wk_h, wk_l);

    // gamma = z @ Wg^T + bg ; beta = z @ Wb^T + bb   [1024x1024, K=256]
    bgemm<<<dim3(16, 8, 1), blk>>>(z, Zd, 0, wg_h, wg_l, Zd, 0, bg, 0,
                                   p_gamma, Fd, 0, Zd, 1.f);
    bgemm<<<dim3(16, 8, 1), blk>>>(z, Zd, 0, wb_h, wb_l, Zd, 0, bb, 0,
                                   p_beta, Fd, 0, Zd, 1.f);
    // h1 = x @ Wl^T + bl   [1024x1024, K=1024]
    bgemm<<<dim3(16, 8, 1), blk>>>(x, Fd, 0, wl_h, wl_l, Fd, 0, bl, 0,
                                   p_h1, Fd, 0, Fd, 1.f);
    // out = LN(h1)*(1+gamma)+beta
    ln_film_kernel<<<1024, blk>>>(p_h1, g1, b1, p_gamma, p_beta, p_out);
    // q = out @ Wq^T + bq
    bgemm<<<dim3(16, 8, 1), blk>>>(p_out, Fd, 0, wq_h, wq_l, Fd, 0, bq, 0,
                                   p_q, Fd, 0, Fd, 1.f);
    // qt[b,h,c] = (1/sqrt(d)) sum_d q[b,h*128+d] * WkT[h,c,d]  (NT, batched h)
    bgemm<<<dim3(12, 8, 8), blk>>>(p_q, Fd, Dh, wk_h, wk_l, Dh, Td * Dh,
                                   nullptr, 0, p_qt, Hn * Td, Td,
                                   Dh, 0.08838834764831845f);
    // fused attention: single pass over text_feat, outputs normalized u[b,h,c]
    cudaFuncSetAttribute(attn_kernel, cudaFuncAttributeMaxDynamicSharedMemorySize,
                         16 * 769 * 4);
    attn_kernel<<<1024, 256, 16 * 769 * 4>>>(text, att, p_qt, p_u);
    // ctx[b,h*128+n] = sum_c u[b,h,c]*Wv[h*128+n,c] + bv  (NT, batched h)
    bgemm<<<dim3(2, 8, 8), blk>>>(p_u, Hn * Td, Td, wv_h, wv_l, Td, Dh * Td,
                                  bv, Dh, p_ctx, Fd, Dh, Td, 1.f);
    // attn_out = ctx @ Wo^T + bo
    bgemm<<<dim3(16, 8, 1), blk>>>(p_ctx, Fd, 0, wo_h, wo_l, Fd, 0, bo, 0,
                                   p_ao, Fd, 0, Fd, 1.f);
    // y = gelu(out + LN(attn_out))
    ln_add_gelu_kernel<<<1024, blk>>>(p_ao, g2, b2, p_out, y);
}

// round 5
// speedup vs baseline: 2.0732x; 1.7366x over previous
#include <cuda_runtime.h>
#include <cuda_bf16.h>
#include <math.h>
#include <stdint.h>

#define Bsz 1024
#define Tsz 128
#define Fd 1024
#define Zd 256
#define Td 768
#define Hn 8
#define Dh 128

// fp32 scratch
__device__ float g_gb[Bsz * 2 * Fd];     // gamma||beta combined [1024, 2048]
__device__ float g_h1[Bsz * Fd];
__device__ float g_out[Bsz * Fd];
__device__ float g_q[Bsz * Fd];
__device__ float g_qt[Bsz * Hn * Td];
__device__ float g_u[Bsz * Hn * Td];
__device__ float g_ctx[Bsz * Fd];
__device__ float g_ao[Bsz * Fd];
__device__ float g_bgb[2 * Fd];          // bg||bb combined bias

// bf16 hi/lo pre-split weights
__device__ __nv_bfloat16 g_Wgb_h[2 * Fd * Zd], g_Wgb_l[2 * Fd * Zd]; // Wg||Wb
__device__ __nv_bfloat16 g_Wl_h[Fd * Fd],  g_Wl_l[Fd * Fd];
__device__ __nv_bfloat16 g_Wq_h[Fd * Fd],  g_Wq_l[Fd * Fd];
__device__ __nv_bfloat16 g_Wo_h[Fd * Fd],  g_Wo_l[Fd * Fd];
__device__ __nv_bfloat16 g_Wv_h[Fd * Td],  g_Wv_l[Fd * Td];
__device__ __nv_bfloat16 g_WkT_h[Hn * Td * Dh], g_WkT_l[Hn * Td * Dh];

// ---------------------------------------------------------------------------
__device__ __forceinline__ uint32_t smem_u32(const void* p) {
    uint32_t a;
    asm("{ .reg .u64 t; cvta.to.shared.u64 t, %1; cvt.u32.u64 %0, t; }"
        : "=r"(a) : "l"(p));
    return a;
}
__device__ __forceinline__ uint32_t pack_bf2(float lo, float hi) {
    uint32_t r;
    asm("cvt.rn.bf16x2.f32 %0, %1, %2;" : "=r"(r) : "f"(hi), "f"(lo));
    return r;
}
__device__ __forceinline__ void mma_bf16(float* c, uint32_t a0, uint32_t a1,
                                         uint32_t a2, uint32_t a3,
                                         uint32_t b0, uint32_t b1) {
    asm volatile(
        "mma.sync.aligned.m16n8k16.row.col.f32.bf16.bf16.f32 "
        "{%0,%1,%2,%3}, {%4,%5,%6,%7}, {%8,%9}, {%0,%1,%2,%3};\n"
        : "+f"(c[0]), "+f"(c[1]), "+f"(c[2]), "+f"(c[3])
        : "r"(a0), "r"(a1), "r"(a2), "r"(a3), "r"(b0), "r"(b1));
}
#define LDSM4(r0, r1, r2, r3, addr) \
    asm volatile("ldmatrix.sync.aligned.m8n8.x4.shared.b16 {%0,%1,%2,%3}, [%4];" \
                 : "=r"(r0), "=r"(r1), "=r"(r2), "=r"(r3) : "r"(addr))

// ===========================================================================
// mma.sync NT GEMM: C[m,n] = alpha * sum_k A[m,k]*B[n,k] + bias[n]
//   A fp32 (split bf16 hi/lo on the fly), B pre-split bf16 hi/lo.
//   3-pass Markidis. BM=128 BN=64 BK=32, 2-stage double buffer,
//   ldmatrix.x4 fragment loads, 1 __syncthreads per chunk. 256 threads.
// ===========================================================================
#define PK 40                 // smem pitch (bf16)
#define AH_OFF 0
#define AL_OFF 10240
#define BH_OFF 20480
#define BL_OFF 25600
#define STG 30720             // stage stride bytes
#define GEMM_SMEM (2 * STG)

__global__ __launch_bounds__(256) void bgemm2(
    const float* __restrict__ A, int lda, int a_bs,
    const __nv_bfloat16* __restrict__ Bh_g, const __nv_bfloat16* __restrict__ Bl_g,
    int ldb, int b_bs,
    const float* __restrict__ bias, int bias_bs,
    float* __restrict__ C, int ldc, int c_bs,
    int K, float alpha)
{
    extern __shared__ char smg[];
    const uint32_t sb = smem_u32(smg);
    const int tid = threadIdx.x, lane = tid & 31, warp = tid >> 5;
    const int wm = warp & 3, wn = warp >> 2;
    const int m0 = blockIdx.y * 128, n0 = blockIdx.x * 64, z = blockIdx.z;

    const float* Ap = A + (size_t)z * a_bs + (size_t)(m0 + (tid >> 1)) * lda
                        + (tid & 1) * 16;
    const __nv_bfloat16* Bph = Bh_g + (size_t)z * b_bs
                        + (size_t)(n0 + (tid >> 2)) * ldb + (tid & 3) * 8;
    const __nv_bfloat16* Bpl = Bl_g + (size_t)z * b_bs
                        + (size_t)(n0 + (tid >> 2)) * ldb + (tid & 3) * 8;

    const int a_sts = ((tid >> 1) * PK + (tid & 1) * 16) * 2;  // bytes
    const int b_sts = ((tid >> 2) * PK + (tid & 3) * 8) * 2;
    const uint32_t a_lds = ((wm * 32 + (lane & 15)) * PK + (lane >> 4) * 8) * 2;
    const uint32_t b_lds = ((wn * 32 + (lane & 15)) * PK + (lane >> 4) * 8) * 2;

    float4 av[4];
    uint4 bvh, bvl;

    auto ldg = [&](int k0) {
        av[0] = *(const float4*)(Ap + k0);
        av[1] = *(const float4*)(Ap + k0 + 4);
        av[2] = *(const float4*)(Ap + k0 + 8);
        av[3] = *(const float4*)(Ap + k0 + 12);
        bvh = *(const uint4*)(Bph + k0);
        bvl = *(const uint4*)(Bpl + k0);
    };
    auto sts = [&](int s) {
        char* base = smg + s * STG;
        const float* af = (const float*)av;
        uint32_t hp[8], lp[8];
#pragma unroll
        for (int j = 0; j < 8; j++) {
            float x0 = af[2 * j], x1 = af[2 * j + 1];
            __nv_bfloat16 h0 = __float2bfloat16(x0), h1 = __float2bfloat16(x1);
            hp[j] = ((uint32_t)__bfloat16_as_ushort(h1) << 16) |
                    __bfloat16_as_ushort(h0);
            lp[j] = pack_bf2(x0 - __bfloat162float(h0), x1 - __bfloat162float(h1));
        }
        *(uint4*)(base + AH_OFF + a_sts)      = make_uint4(hp[0], hp[1], hp[2], hp[3]);
        *(uint4*)(base + AH_OFF + a_sts + 16) = make_uint4(hp[4], hp[5], hp[6], hp[7]);
        *(uint4*)(base + AL_OFF + a_sts)      = make_uint4(lp[0], lp[1], lp[2], lp[3]);
        *(uint4*)(base + AL_OFF + a_sts + 16) = make_uint4(lp[4], lp[5], lp[6], lp[7]);
        *(uint4*)(base + BH_OFF + b_sts) = bvh;
        *(uint4*)(base + BL_OFF + b_sts) = bvl;
    };

    float acc[2][4][4] = {};
    const int nch = K >> 5;

    ldg(0);
    sts(0);
    __syncthreads();

    for (int c = 0; c < nch; ++c) {
        const int buf = c & 1;
        if (c + 1 < nch) ldg((c + 1) << 5);

        const uint32_t ab = sb + buf * STG + a_lds;
        const uint32_t bb = sb + buf * STG + BH_OFF + b_lds;
#pragma unroll
        for (int kk = 0; kk < 2; kk++) {
            const uint32_t ko = kk * 32;  // byte offset (16 bf16)
            uint32_t ah[2][4], al[2][4], bh[2][4], bl[2][4];
#pragma unroll
            for (int mr = 0; mr < 2; mr++) {
                LDSM4(ah[mr][0], ah[mr][1], ah[mr][2], ah[mr][3],
                      ab + mr * 1280 + ko);
                LDSM4(al[mr][0], al[mr][1], al[mr][2], al[mr][3],
                      ab + AL_OFF + mr * 1280 + ko);
            }
#pragma unroll
            for (int nb = 0; nb < 2; nb++) {
                LDSM4(bh[nb][0], bh[nb][1], bh[nb][2], bh[nb][3],
                      bb + nb * 1280 + ko);
                LDSM4(bl[nb][0], bl[nb][1], bl[nb][2], bl[nb][3],
                      bb + (BL_OFF - BH_OFF) + nb * 1280 + ko);
            }
#pragma unroll
            for (int mr = 0; mr < 2; mr++)
#pragma unroll
                for (int nb = 0; nb < 2; nb++) {
                    float* c0 = acc[mr][2 * nb];
                    float* c1 = acc[mr][2 * nb + 1];
                    mma_bf16(c0, ah[mr][0], ah[mr][1], ah[mr][2], ah[mr][3],
                             bh[nb][0], bh[nb][2]);
                    mma_bf16(c0, ah[mr][0], ah[mr][1], ah[mr][2], ah[mr][3],
                             bl[nb][0], bl[nb][2]);
                    mma_bf16(c0, al[mr][0], al[mr][1], al[mr][2], al[mr][3],
                             bh[nb][0], bh[nb][2]);
                    mma_bf16(c1, ah[mr][0], ah[mr][1], ah[mr][2], ah[mr][3],
                             bh[nb][1], bh[nb][3]);
                    mma_bf16(c1, ah[mr][0], ah[mr][1], ah[mr][2], ah[mr][3],
                             bl[nb][1], bl[nb][3]);
                    mma_bf16(c1, al[mr][0], al[mr][1], al[mr][2], al[mr][3],
                             bh[nb][1], bh[nb][3]);
                }
        }
        if (c + 1 < nch) sts((c + 1) & 1);
        __syncthreads();
    }

    // epilogue
    const int gid = lane >> 2, tig = lane & 3;
#pragma unroll
    for (int mr = 0; mr < 2; mr++) {
#pragma unroll
        for (int nc = 0; nc < 4; nc++) {
            int m = m0 + wm * 32 + mr * 16 + gid;
            int n = n0 + wn * 32 + nc * 8 + tig * 2;
            float b0 = 0.f, b1 = 0.f;
            if (bias) {
                b0 = bias[(size_t)z * bias_bs + n];
                b1 = bias[(size_t)z * bias_bs + n + 1];
            }
            float2 o0, o1;
            o0.x = fmaf(acc[mr][nc][0], alpha, b0);
            o0.y = fmaf(acc[mr][nc][1], alpha, b1);
            o1.x = fmaf(acc[mr][nc][2], alpha, b0);
            o1.y = fmaf(acc[mr][nc][3], alpha, b1);
            *(float2*)&C[(size_t)z * c_bs + (size_t)m * ldc + n] = o0;
            *(float2*)&C[(size_t)z * c_bs + (size_t)(m + 8) * ldc + n] = o1;
        }
    }
}

// ---------------------------------------------------------------------------
// Split fp32 -> bf16 hi + lo
// ---------------------------------------------------------------------------
__global__ __launch_bounds__(256) void split_kernel(
    const float* __restrict__ w, __nv_bfloat16* __restrict__ h,
    __nv_bfloat16* __restrict__ l)
{
    int i = (blockIdx.x * 256 + threadIdx.x) * 4;
    float4 v = *(const float4*)(w + i);
    float vv[4] = {v.x, v.y, v.z, v.w};
#pragma unroll
    for (int j = 0; j < 4; j++) {
        __nv_bfloat16 hi = __float2bfloat16(vv[j]);
        h[i + j] = hi;
        l[i + j] = __float2bfloat16(vv[j] - __bfloat162float(hi));
    }
}

// Split + transpose Wk: out[(hh*768 + c)*128 + d] = Wk[(hh*128 + d)*768 + c]
__global__ __launch_bounds__(256) void splitT_wk(
    const float* __restrict__ w, __nv_bfloat16* __restrict__ h,
    __nv_bfloat16* __restrict__ l)
{
    int idx = blockIdx.x * 256 + threadIdx.x;
    int d = idx & 127;
    int c = (idx >> 7) % Td;
    int hh = idx / (128 * Td);
    float v = w[((size_t)hh * 128 + d) * Td + c];
    __nv_bfloat16 hi = __float2bfloat16(v);
    h[idx] = hi;
    l[idx] = __float2bfloat16(v - __bfloat162float(hi));
}

// ---------------------------------------------------------------------------
// LayerNorm(h1)*g+b then FiLM with gamma/beta from combined gb buffer
// ---------------------------------------------------------------------------
__global__ __launch_bounds__(256) void ln_film_kernel(
    const float* __restrict__ h1, const float* __restrict__ g,
    const float* __restrict__ bb, const float* __restrict__ gb,
    float* __restrict__ out)
{
    int r = blockIdx.x, tid = threadIdx.x;
    __shared__ float red1[8], red2[8], mv[2];
    const float* row = h1 + (size_t)r * Fd;
    float v[4], s = 0.f, s2 = 0.f;
#pragma unroll
    for (int i = 0; i < 4; i++) {
        v[i] = row[tid + i * 256];
        s += v[i]; s2 += v[i] * v[i];
    }
#pragma unroll
    for (int o = 16; o; o >>= 1) {
        s += __shfl_xor_sync(~0u, s, o);
        s2 += __shfl_xor_sync(~0u, s2, o);
    }
    if ((tid & 31) == 0) { red1[tid >> 5] = s; red2[tid >> 5] = s2; }
    __syncthreads();
    if (tid == 0) {
        float a = 0.f, b2 = 0.f;
        for (int w = 0; w < 8; w++) { a += red1[w]; b2 += red2[w]; }
        mv[0] = a * (1.f / Fd); mv[1] = b2 * (1.f / Fd);
    }
    __syncthreads();
    float mu = mv[0], var = mv[1] - mu * mu;
    float rstd = rsqrtf(var + 1e-5f);
#pragma unroll
    for (int i = 0; i < 4; i++) {
        int f = tid + i * 256;
        float y = (v[i] - mu) * rstd * g[f] + bb[f];
        float gamma = gb[(size_t)r * 2048 + f];
        float beta  = gb[(size_t)r * 2048 + 1024 + f];
        out[(size_t)r * Fd + f] = y * (1.f + gamma) + beta;
    }
}

// ---------------------------------------------------------------------------
// y = gelu(res + LayerNorm(ao)*g + b)
// ---------------------------------------------------------------------------
__global__ __launch_bounds__(256) void ln_add_gelu_kernel(
    const float* __restrict__ ao, const float* __restrict__ g,
    const float* __restrict__ bb, const float* __restrict__ res,
    float* __restrict__ y)
{
    int r = blockIdx.x, tid = threadIdx.x;
    __shared__ float red1[8], red2[8], mv[2];
    const float* row = ao + (size_t)r * Fd;
    float v[4], s = 0.f, s2 = 0.f;
#pragma unroll
    for (int i = 0; i < 4; i++) {
        v[i] = row[tid + i * 256];
        s += v[i]; s2 += v[i] * v[i];
    }
#pragma unroll
    for (int o = 16; o; o >>= 1) {
        s += __shfl_xor_sync(~0u, s, o);
        s2 += __shfl_xor_sync(~0u, s2, o);
    }
    if ((tid & 31) == 0) { red1[tid >> 5] = s; red2[tid >> 5] = s2; }
    __syncthreads();
    if (tid == 0) {
        float a = 0.f, b2 = 0.f;
        for (int w = 0; w < 8; w++) { a += red1[w]; b2 += red2[w]; }
        mv[0] = a * (1.f / Fd); mv[1] = b2 * (1.f / Fd);
    }
    __syncthreads();
    float mu = mv[0], var = mv[1] - mu * mu;
    float rstd = rsqrtf(var + 1e-5f);
#pragma unroll
    for (int i = 0; i < 4; i++) {
        int f = tid + i * 256;
        float t = res[(size_t)r * Fd + f] + ((v[i] - mu) * rstd * g[f] + bb[f]);
        y[(size_t)r * Fd + f] = t * normcdff(t);
    }
}

// ---------------------------------------------------------------------------
// Fused attention v4: score pass per-head warp; u-pass c-split across warps
// (each warp owns 96 channels, updates all 8 heads from p broadcast).
// Text read from HBM exactly once; smem traffic ~2x lower than v1.
// ---------------------------------------------------------------------------
#define ATTN_SMEM (16 * 768 * 4 + (128 + 8 + 8) * 4)

__global__ __launch_bounds__(256) void attn_kernel(
    const float* __restrict__ text, const int* __restrict__ att,
    const float* __restrict__ qt, float* __restrict__ u)
{
    extern __shared__ float sma[];
    float* tile = sma;                   // [16][768]
    float* p_sm = sma + 16 * 768;        // [16][8]  (t*8 + h)
    float* rs_sm = p_sm + 128;           // [8]
    float* il_sm = rs_sm + 8;            // [8]
    __shared__ int s_att[128];

    const int b = blockIdx.x, tid = threadIdx.x;
    const int w = tid >> 5, lane = tid & 31;   // w = head (score) = c-group (u)
    const int cw = w * 96;

    float qreg[24];
    const float* qrow = qt + (size_t)b * (Hn * Td) + w * Td + lane;
#pragma unroll
    for (int i = 0; i < 24; i++) qreg[i] = qrow[32 * i];

    float ureg[8][3];
#pragma unroll
    for (int hh = 0; hh < 8; hh++)
#pragma unroll
        for (int j = 0; j < 3; j++) ureg[hh][j] = 0.f;

    for (int i = tid; i < 128; i += 256) s_att[i] = att[b * 128 + i];

    float m_run = -INFINITY, l_run = 0.f;
    const float* tb = text + (size_t)b * Tsz * Td;

    for (int tc = 0; tc < 8; tc++) {
        __syncthreads();  // prior u-pass consumers done
        for (int i = tid; i < 3072; i += 256) {
            *(float4*)&tile[i * 4] = *(const float4*)(tb + tc * 12288 + i * 4);
        }
        __syncthreads();

        // ---- score pass: head = warp ----
        float sc[16];
#pragma unroll
        for (int t = 0; t < 16; t++) {
            float a = 0.f;
            const float* tr = tile + t * 768 + lane;
#pragma unroll
            for (int i = 0; i < 24; i++) a = fmaf(qreg[i], tr[32 * i], a);
            sc[t] = a;
        }
#pragma unroll
        for (int t = 0; t < 16; t++)
#pragma unroll
            for (int o = 16; o; o >>= 1) sc[t] += __shfl_xor_sync(~0u, sc[t], o);

        float mx = m_run;
#pragma unroll
        for (int t = 0; t < 16; t++) {
            if (s_att[tc * 16 + t] == 0) sc[t] = -INFINITY;
            mx = fmaxf(mx, sc[t]);
        }
        float p[16], rs;
        if (mx == -INFINITY) {
            rs = 1.f;
#pragma unroll
            for (int t = 0; t < 16; t++) p[t] = 0.f;
        } else {
            rs = expf(m_run - mx);
#pragma unroll
            for (int t = 0; t < 16; t++)
                p[t] = (sc[t] == -INFINITY) ? 0.f : expf(sc[t] - mx);
        }
        float ps = 0.f;
#pragma unroll
        for (int t = 0; t < 16; t++) ps += p[t];
        l_run = l_run * rs + ps;
        m_run = mx;

        // publish p (lane t writes p[t]) and rs
#pragma unroll
        for (int t = 0; t < 16; t++)
            if (lane == t) p_sm[t * 8 + w] = p[t];
        if (lane == 16) rs_sm[w] = rs;
        __syncthreads();

        // ---- u pass: c-split, all heads ----
        float rsv[8];
#pragma unroll
        for (int hh = 0; hh < 8; hh++) rsv[hh] = rs_sm[hh];
#pragma unroll
        for (int hh = 0; hh < 8; hh++)
#pragma unroll
            for (int j = 0; j < 3; j++) ureg[hh][j] *= rsv[hh];

#pragma unroll
        for (int t = 0; t < 16; t++) {
            const float* tr = tile + t * 768 + cw + lane;
            float x0 = tr[0], x1 = tr[32], x2 = tr[64];
            float4 pa = *(float4*)&p_sm[t * 8];
            float4 pb = *(float4*)&p_sm[t * 8 + 4];
            float pv[8] = {pa.x, pa.y, pa.z, pa.w, pb.x, pb.y, pb.z, pb.w};
#pragma unroll
            for (int hh = 0; hh < 8; hh++) {
                ureg[hh][0] = fmaf(pv[hh], x0, ureg[hh][0]);
                ureg[hh][1] = fmaf(pv[hh], x1, ureg[hh][1]);
                ureg[hh][2] = fmaf(pv[hh], x2, ureg[hh][2]);
            }
        }
    }

    if (lane == 0) il_sm[w] = 1.f / l_run;
    __syncthreads();

    float* ub = u + (size_t)b * (Hn * Td);
#pragma unroll
    for (int hh = 0; hh < 8; hh++) {
        float il = il_sm[hh];
#pragma unroll
        for (int j = 0; j < 3; j++)
            ub[hh * Td + cw + lane + 32 * j] = ureg[hh][j] * il;
    }
}

// ---------------------------------------------------------------------------
extern "C" void kernel_launch(void* const* d_in, const int* in_sizes, int n_in,
                              void* d_out, int out_size)
{
    const float* x    = (const float*)d_in[0];
    const float* z    = (const float*)d_in[1];
    const float* text = (const float*)d_in[2];
    const int*   att  = (const int*)d_in[3];
    const float* Wg = (const float*)d_in[4];  const float* bg = (const float*)d_in[5];
    const float* Wb = (const float*)d_in[6];  const float* bb = (const float*)d_in[7];
    const float* Wl = (const float*)d_in[8];  const float* bl = (const float*)d_in[9];
    const float* g1 = (const float*)d_in[10]; const float* b1 = (const float*)d_in[11];
    const float* Wq = (const float*)d_in[12]; const float* bq = (const float*)d_in[13];
    const float* Wk = (const float*)d_in[14]; /* bk softmax-invariant: dropped */
    const float* Wv = (const float*)d_in[16]; const float* bv = (const float*)d_in[17];
    const float* Wo = (const float*)d_in[18]; const float* bo = (const float*)d_in[19];
    const float* g2 = (const float*)d_in[20]; const float* b2 = (const float*)d_in[21];
    float* y = (float*)d_out;

    float *p_gb, *p_h1, *p_out, *p_q, *p_qt, *p_u, *p_ctx, *p_ao, *p_bgb;
    cudaGetSymbolAddress((void**)&p_gb,  g_gb);
    cudaGetSymbolAddress((void**)&p_h1,  g_h1);
    cudaGetSymbolAddress((void**)&p_out, g_out);
    cudaGetSymbolAddress((void**)&p_q,   g_q);
    cudaGetSymbolAddress((void**)&p_qt,  g_qt);
    cudaGetSymbolAddress((void**)&p_u,   g_u);
    cudaGetSymbolAddress((void**)&p_ctx, g_ctx);
    cudaGetSymbolAddress((void**)&p_ao,  g_ao);
    cudaGetSymbolAddress((void**)&p_bgb, g_bgb);

    __nv_bfloat16 *wgb_h, *wgb_l, *wl_h, *wl_l, *wq_h, *wq_l;
    __nv_bfloat16 *wo_h, *wo_l, *wv_h, *wv_l, *wk_h, *wk_l;
    cudaGetSymbolAddress((void**)&wgb_h, g_Wgb_h);
    cudaGetSymbolAddress((void**)&wgb_l, g_Wgb_l);
    cudaGetSymbolAddress((void**)&wl_h, g_Wl_h); cudaGetSymbolAddress((void**)&wl_l, g_Wl_l);
    cudaGetSymbolAddress((void**)&wq_h, g_Wq_h); cudaGetSymbolAddress((void**)&wq_l, g_Wq_l);
    cudaGetSymbolAddress((void**)&wo_h, g_Wo_h); cudaGetSymbolAddress((void**)&wo_l, g_Wo_l);
    cudaGetSymbolAddress((void**)&wv_h, g_Wv_h); cudaGetSymbolAddress((void**)&wv_l, g_Wv_l);
    cudaGetSymbolAddress((void**)&wk_h, g_WkT_h); cudaGetSymbolAddress((void**)&wk_l, g_WkT_l);

    cudaFuncSetAttribute(bgemm2, cudaFuncAttributeMaxDynamicSharedMemorySize,
                         GEMM_SMEM);
    cudaFuncSetAttribute(attn_kernel, cudaFuncAttributeMaxDynamicSharedMemorySize,
                         ATTN_SMEM);

    dim3 blk(256);

    // weight pre-split; Wg||Wb combined, Wk transposed per head
    split_kernel<<<(Fd * Zd) / 1024, blk>>>(Wg, wgb_h, wgb_l);
    split_kernel<<<(Fd * Zd) / 1024, blk>>>(Wb, wgb_h + Fd * Zd, wgb_l + Fd * Zd);
    split_kernel<<<(Fd * Fd) / 1024, blk>>>(Wl, wl_h, wl_l);
    split_kernel<<<(Fd * Fd) / 1024, blk>>>(Wq, wq_h, wq_l);
    split_kernel<<<(Fd * Fd) / 1024, blk>>>(Wo, wo_h, wo_l);
    split_kernel<<<(Fd * Td) / 1024, blk>>>(Wv, wv_h, wv_l);
    splitT_wk<<<(Hn * Td * Dh) / 256, blk>>>(Wk, wk_h, wk_l);
    // combined bias bg||bb
    cudaMemcpyAsync(p_bgb, bg, Fd * sizeof(float), cudaMemcpyDeviceToDevice);
    cudaMemcpyAsync(p_bgb + Fd, bb, Fd * sizeof(float), cudaMemcpyDeviceToDevice);

    // gamma||beta = z @ [Wg;Wb]^T + [bg;bb]   [1024 x 2048, K=256]
    bgemm2<<<dim3(32, 8, 1), blk, GEMM_SMEM>>>(z, Zd, 0, wgb_h, wgb_l, Zd, 0,
                                               p_bgb, 0, p_gb, 2 * Fd, 0, Zd, 1.f);
    // h1 = x @ Wl^T + bl
    bgemm2<<<dim3(16, 8, 1), blk, GEMM_SMEM>>>(x, Fd, 0, wl_h, wl_l, Fd, 0, bl, 0,
                                               p_h1, Fd, 0, Fd, 1.f);
    // out = LN(h1)*(1+gamma)+beta
    ln_film_kernel<<<1024, blk>>>(p_h1, g1, b1, p_gb, p_out);
    // q = out @ Wq^T + bq
    bgemm2<<<dim3(16, 8, 1), blk, GEMM_SMEM>>>(p_out, Fd, 0, wq_h, wq_l, Fd, 0,
                                               bq, 0, p_q, Fd, 0, Fd, 1.f);
    // qt = (1/sqrt(d)) q_h @ WkT_h  (batched over heads)
    bgemm2<<<dim3(12, 8, 8), blk, GEMM_SMEM>>>(p_q, Fd, Dh, wk_h, wk_l, Dh,
                                               Td * Dh, nullptr, 0,
                                               p_qt, Hn * Td, Td, Dh,
                                               0.08838834764831845f);
    // fused attention
    attn_kernel<<<1024, blk, ATTN_SMEM>>>(text, att, p_qt, p_u);
    // ctx = u @ Wv^T + bv  (batched over heads)
    bgemm2<<<dim3(2, 8, 8), blk, GEMM_SMEM>>>(p_u, Hn * Td, Td, wv_h, wv_l, Td,
                                              Dh * Td, bv, Dh,
                                              p_ctx, Fd, Dh, Td, 1.f);
    // attn_out = ctx @ Wo^T + bo
    bgemm2<<<dim3(16, 8, 1), blk, GEMM_SMEM>>>(p_ctx, Fd, 0, wo_h, wo_l, Fd, 0,
                                               bo, 0, p_ao, Fd, 0, Fd, 1.f);
    // y = gelu(out + LN(attn_out))
    ln_add_gelu_kernel<<<1024, blk>>>(p_ao, g2, b2, p_out, y);
}